// round 12
// baseline (speedup 1.0000x reference)
#include <cuda_runtime.h>
#include <math.h>

// predicts/targets (2,4,64,256,256) f32, masks (2,1,64,256,256) f32 -> scalar f32.
// Identities (validated R2..R10, rel_err ~1e-7):
//   omega_pred - omega_trgt = vorticity(scale*(P-T));  scale/(2*delta)=1
//   voxel counts & contributes <=> all 27 masks in 3x3x3 neighborhood == 1
// R11: software-pipelined — prefetch plane z+2 LDGs before consuming plane z;
//      masks live in stager registers (no sM smem); one sync per z-step.
namespace {
constexpr int Bn = 2, Cn = 4, Dn = 64, Hn = 256, Wn = 256;
constexpr long long CH = (long long)Dn * Hn * Wn;
constexpr int TY  = 7;                   // output rows per block
constexpr int RWS = 9;                   // staged rows (TY + 2 halo)
constexpr int NYT = 37;                  // 37*7 = 259 >= 254
constexpr int ZC  = 4;                   // z-chunks per batch (16,16,16,14)
constexpr int NBLK = NYT * 2 * ZC;       // 296 = 2 blocks/SM * 148 SMs
constexpr int PLF  = RWS * Wn;           // elems per staged plane (2304)
// dynamic smem layout (bytes)
constexpr int OFF_U  = 0;                       // 4 f32 planes (consume z-1..z+1, stage z+2)
constexpr int OFF_V  = OFF_U  + 4 * PLF * 4;    // 4 f32 planes
constexpr int OFF_W  = OFF_V  + 4 * PLF * 4;    // 3 f32 planes (consume z, stage z+2)
constexpr int OFF_CP = OFF_W  + 3 * PLF * 4;    // 2 u8 planes (3z column AND)
constexpr int SMEM_BYTES = OFF_CP + 2 * PLF;    // 105984 B -> 2 blocks/SM
}

__device__ float        g_psum[NBLK];
__device__ unsigned int g_pcnt[NBLK];
__device__ unsigned int g_ticket = 0;

__device__ __forceinline__ float4 f4sub(const float4 a, const float4 b) {
    return make_float4(a.x - b.x, a.y - b.y, a.z - b.z, a.w - b.w);
}
__device__ __forceinline__ unsigned packm(const float4 m) {
    return (m.x > 0.5f ? 1u : 0u)       | (m.y > 0.5f ? 1u : 0u) << 8
         | (m.z > 0.5f ? 1u : 0u) << 16 | (m.w > 0.5f ? 1u : 0u) << 24;
}

__global__ __launch_bounds__(512, 2)
void k_main(const float* __restrict__ P,
            const float* __restrict__ T,
            const float* __restrict__ M,
            float* __restrict__ out) {
    extern __shared__ unsigned char smem[];
    float*         sU  = (float*)(smem + OFF_U);
    float*         sV  = (float*)(smem + OFF_V);
    float*         sW  = (float*)(smem + OFF_W);
    unsigned char* sCP = smem + OFF_CP;

    const int tid = threadIdx.x;
    const int b   = blockIdx.y / ZC;
    const int zi  = blockIdx.y % ZC;
    const int z0  = 1 + zi * 16;
    const int z1  = min(z0 + 15, Dn - 2);         // chunks: 16,16,16,14
    const int y0  = 1 + blockIdx.x * TY;

    const float* mb = M + (long long)b * CH;
    const float* uP = P + ((long long)b * Cn + 1) * CH;
    const float* uT = T + ((long long)b * Cn + 1) * CH;
    const float* vP = uP + CH;  const float* vT = uT + CH;
    const float* wP = vP + CH;  const float* wT = vT + CH;

    // this thread's fixed staging slot (rows 0..7); extras cover row 8
    const int  r0   = tid >> 6;
    const int  x40  = (tid & 63) << 2;
    const int  ro   = r0 * Wn + x40;
    const long long rowb = (long long)min(y0 - 1 + r0, Hn - 1) * Wn + x40;
    const bool extra = (tid & 7) == 0;
    const int  rox   = 8 * Wn + ((tid >> 3) << 2);
    const long long rowbx = (long long)min(y0 + 7, Hn - 1) * Wn + ((tid >> 3) << 2);

    // ---- prologue: u,v planes z0-1..z0+1 ; w planes z0,z0+1 ; CP(z0) ----
    unsigned ma, mbm, max_ = 0u, mbx = 0u;
    {
        unsigned mzm = 0u, mzmx = 0u;
        #pragma unroll
        for (int k = 0; k < 3; ++k) {
            const int zz = z0 - 1 + k;
            const long long pb = (long long)zz * (Hn * Wn) + rowb;
            sU[(zz & 3) * PLF + ro] = f4sub(*(const float4*)(uP + pb), *(const float4*)(uT + pb)).x,
            *(float4*)(sU + (zz & 3) * PLF + ro) = f4sub(*(const float4*)(uP + pb), *(const float4*)(uT + pb));
            *(float4*)(sV + (zz & 3) * PLF + ro) = f4sub(*(const float4*)(vP + pb), *(const float4*)(vT + pb));
            if (k >= 1)
                *(float4*)(sW + (zz % 3) * PLF + ro) = f4sub(*(const float4*)(wP + pb), *(const float4*)(wT + pb));
            const unsigned mw = packm(*(const float4*)(mb + pb));
            if (k == 0) mzm = mw; else if (k == 1) ma = mw; else mbm = mw;
            if (extra) {
                const long long pbx = (long long)zz * (Hn * Wn) + rowbx;
                *(float4*)(sU + (zz & 3) * PLF + rox) = f4sub(*(const float4*)(uP + pbx), *(const float4*)(uT + pbx));
                *(float4*)(sV + (zz & 3) * PLF + rox) = f4sub(*(const float4*)(vP + pbx), *(const float4*)(vT + pbx));
                if (k >= 1)
                    *(float4*)(sW + (zz % 3) * PLF + rox) = f4sub(*(const float4*)(wP + pbx), *(const float4*)(wT + pbx));
                const unsigned mwx = packm(*(const float4*)(mb + pbx));
                if (k == 0) mzmx = mwx; else if (k == 1) max_ = mwx; else mbx = mwx;
            }
        }
        *(unsigned*)(sCP + (z0 & 1) * PLF + ro) = mzm & ma & mbm;
        if (extra) *(unsigned*)(sCP + (z0 & 1) * PLF + rox) = mzmx & max_ & mbx;
    }
    __syncthreads();

    float fs  = 0.f;
    int   cnt = 0;
    const int x    = tid & 255;
    const int half = tid >> 8;
    const int rlo  = (half == 0) ? 1 : 5;
    const int rhi  = (half == 0) ? 4 : 7;

    for (int z = z0; z <= z1; ++z) {
        // ---- prefetch plane z+2 (independent of smem; overlaps consume) ----
        const int zz2 = min(z + 2, Dn - 1);
        const long long pb = (long long)zz2 * (Hn * Wn) + rowb;
        const float4 lup = *(const float4*)(uP + pb);
        const float4 lut = *(const float4*)(uT + pb);
        const float4 lvp = *(const float4*)(vP + pb);
        const float4 lvt = *(const float4*)(vT + pb);
        const float4 lwp = *(const float4*)(wP + pb);
        const float4 lwt = *(const float4*)(wT + pb);
        const float4 lm  = *(const float4*)(mb + pb);

        // ---- consume plane z (R9 scalar; disjoint slots from the STS below) ----
        {
            const int sz = z & 3, szp = (z + 1) & 3, szm = (z - 1) & 3;
            const int swz = z % 3;
            const unsigned char* cp = sCP + (z & 1) * PLF;
            if (x >= 1 && x <= Wn - 2) {
                #pragma unroll
                for (int r = rlo; r <= rhi; ++r) {
                    const int y = y0 - 1 + r;
                    if (y > Hn - 2) break;
                    const int ok = (int)cp[(r - 1) * Wn + x - 1] & cp[(r - 1) * Wn + x]
                                 & cp[(r - 1) * Wn + x + 1]
                                 & cp[r * Wn + x - 1] & cp[r * Wn + x] & cp[r * Wn + x + 1]
                                 & cp[(r + 1) * Wn + x - 1] & cp[(r + 1) * Wn + x]
                                 & cp[(r + 1) * Wn + x + 1];

                    const float dyU = sU[sz * PLF + (r + 1) * Wn + x] - sU[sz * PLF + (r - 1) * Wn + x];
                    const float dzU = sU[szp * PLF + r * Wn + x]      - sU[szm * PLF + r * Wn + x];
                    const float dyW = sW[swz * PLF + (r + 1) * Wn + x] - sW[swz * PLF + (r - 1) * Wn + x];
                    const float dxW = sW[swz * PLF + r * Wn + x + 1]   - sW[swz * PLF + r * Wn + x - 1];
                    const float dxV = sV[sz * PLF + r * Wn + x + 1]    - sV[sz * PLF + r * Wn + x - 1];
                    const float dzV = sV[szp * PLF + r * Wn + x]       - sV[szm * PLF + r * Wn + x];

                    const float ox = dyW - dzV;
                    const float oy = dzU - dxW;
                    const float oz = dxV - dyU;
                    fs  += (float)ok * sqrtf(ox * ox + oy * oy + oz * oz);
                    cnt += ok;
                }
            }
        }

        // ---- STS plane z+2; CP(z+1) from register masks ----
        {
            const int s4 = (z + 2) & 3, sw3 = (z + 2) % 3;
            *(float4*)(sU + s4 * PLF + ro)  = f4sub(lup, lut);
            *(float4*)(sV + s4 * PLF + ro)  = f4sub(lvp, lvt);
            *(float4*)(sW + sw3 * PLF + ro) = f4sub(lwp, lwt);
            const unsigned mc = packm(lm);
            *(unsigned*)(sCP + ((z + 1) & 1) * PLF + ro) = ma & mbm & mc;
            ma = mbm; mbm = mc;
            if (extra) {
                const long long pbx = (long long)zz2 * (Hn * Wn) + rowbx;
                *(float4*)(sU + s4 * PLF + rox)  = f4sub(*(const float4*)(uP + pbx), *(const float4*)(uT + pbx));
                *(float4*)(sV + s4 * PLF + rox)  = f4sub(*(const float4*)(vP + pbx), *(const float4*)(vT + pbx));
                *(float4*)(sW + sw3 * PLF + rox) = f4sub(*(const float4*)(wP + pbx), *(const float4*)(wT + pbx));
                const unsigned mcx = packm(*(const float4*)(mb + pbx));
                *(unsigned*)(sCP + ((z + 1) & 1) * PLF + rox) = max_ & mbx & mcx;
                max_ = mbx; mbx = mcx;
            }
        }
        __syncthreads();   // orders STS(z+2)/CP(z+1) before consume(z+1)
    }

    // ---- block reduction (16 warps) -> partial; last block finalizes ----
    #pragma unroll
    for (int off = 16; off; off >>= 1) {
        fs  += __shfl_down_sync(0xffffffffu, fs,  off);
        cnt += __shfl_down_sync(0xffffffffu, cnt, off);
    }
    __shared__ float ws[16];
    __shared__ int   wc2[16];
    __shared__ bool  sLast;
    const int wid = tid >> 5, lid = tid & 31;
    if (lid == 0) { ws[wid] = fs; wc2[wid] = cnt; }
    __syncthreads();
    if (wid == 0) {
        fs  = (lid < 16) ? ws[lid]  : 0.f;
        cnt = (lid < 16) ? wc2[lid] : 0;
        #pragma unroll
        for (int off = 8; off; off >>= 1) {
            fs  += __shfl_down_sync(0xffffffffu, fs,  off);
            cnt += __shfl_down_sync(0xffffffffu, cnt, off);
        }
        if (lid == 0) {
            const int slot = blockIdx.y * NYT + blockIdx.x;
            g_psum[slot] = fs;
            g_pcnt[slot] = (unsigned)cnt;
            __threadfence();
            const unsigned t = atomicAdd(&g_ticket, 1u);
            sLast = (t == NBLK - 1);
        }
    }
    __syncthreads();

    if (sLast) {
        // Deterministic final reduce: fixed order over 296 slots, double accum.
        double             s = (tid < NBLK) ? (double)__ldcg(&g_psum[tid]) : 0.0;
        unsigned long long c = (tid < NBLK) ? (unsigned long long)__ldcg(&g_pcnt[tid]) : 0ull;
        #pragma unroll
        for (int off = 16; off; off >>= 1) {
            s += __shfl_down_sync(0xffffffffu, s, off);
            c += __shfl_down_sync(0xffffffffu, c, off);
        }
        __shared__ double             ds[16];
        __shared__ unsigned long long dc[16];
        if (lid == 0) { ds[wid] = s; dc[wid] = c; }
        __syncthreads();
        if (wid == 0) {
            s = (lid < 16) ? ds[lid] : 0.0;
            c = (lid < 16) ? dc[lid] : 0ull;
            #pragma unroll
            for (int off = 8; off; off >>= 1) {
                s += __shfl_down_sync(0xffffffffu, s, off);
                c += __shfl_down_sync(0xffffffffu, c, off);
            }
            if (lid == 0) {
                out[0] = (float)(s / (double)c);
                g_ticket = 0;                     // reset for next graph replay
            }
        }
    }
}

extern "C" void kernel_launch(void* const* d_in, const int* in_sizes, int n_in,
                              void* d_out, int out_size) {
    const float* P = (const float*)d_in[0];
    const float* T = (const float*)d_in[1];
    const float* M = (const float*)d_in[2];
    float*       O = (float*)d_out;

    cudaFuncSetAttribute(k_main, cudaFuncAttributeMaxDynamicSharedMemorySize, SMEM_BYTES);
    k_main<<<dim3(NYT, 2 * ZC), 512, SMEM_BYTES>>>(P, T, M, O);
}

// round 13
// speedup vs baseline: 1.2735x; 1.2735x over previous
#include <cuda_runtime.h>
#include <math.h>

// predicts/targets (2,4,64,256,256) f32, masks (2,1,64,256,256) f32 -> scalar f32.
// Identities (validated R2..R11, rel_err ~1e-7):
//   omega_pred - omega_trgt = vorticity(scale*(P-T));  scale/(2*delta)=1
//   voxel counts & contributes <=> all 27 masks in 3x3x3 neighborhood == 1
// R12: 3 blocks/SM (384 thr, 63KB smem). w ring depth-1, masks in stager regs,
//      CP bit-packed via shfl; unconditional scalar consume (R9-style).
namespace {
constexpr int Bn = 2, Cn = 4, Dn = 64, Hn = 256, Wn = 256;
constexpr long long CH = (long long)Dn * Hn * Wn;
constexpr int HW  = Hn * Wn;
constexpr int TY  = 7;                   // output rows per block
constexpr int RWS = 9;                   // staged rows (TY + 2 halo)
constexpr int NYT = 37;                  // 37*7 = 259 >= 254
constexpr int ZC  = 6;                   // z-chunks per batch (11,11,10,10,10,10)
constexpr int NBLK = NYT * 2 * ZC;       // 444 = 3 blocks/SM * 148 SMs exactly
constexpr int PLF  = RWS * Wn;           // 2304 elems per staged plane
constexpr int CPW  = 10;                 // words per CP row (8 data + 2 pad)
constexpr int SMEM_BYTES = 7 * PLF * 4 + 96 * 4;   // u(3)+v(3)+w(1) f32 + CP bits
}

__device__ float        g_psum[NBLK];
__device__ unsigned int g_pcnt[NBLK];
__device__ unsigned int g_ticket = 0;

__device__ __forceinline__ float4 f4sub(const float4 a, const float4 b) {
    return make_float4(a.x - b.x, a.y - b.y, a.z - b.z, a.w - b.w);
}
__device__ __forceinline__ unsigned packm(const float4 m) {
    return (m.x > 0.5f ? 1u : 0u)       | (m.y > 0.5f ? 1u : 0u) << 8
         | (m.z > 0.5f ? 1u : 0u) << 16 | (m.w > 0.5f ? 1u : 0u) << 24;
}
// 4 mask-AND bytes -> 4-bit nibble
__device__ __forceinline__ unsigned nib4(unsigned c) {
    return (c & 1u) | ((c >> 7) & 2u) | ((c >> 14) & 4u) | ((c >> 21) & 8u);
}

__global__ __launch_bounds__(384, 3)
void k_main(const float* __restrict__ P,
            const float* __restrict__ T,
            const float* __restrict__ M,
            float* __restrict__ out) {
    extern __shared__ float smemf[];
    float*    sU  = smemf;                 // 3 planes
    float*    sV  = sU + 3 * PLF;          // 3 planes
    float*    sW  = sV + 3 * PLF;          // 1 plane
    unsigned* sCP = (unsigned*)(sW + PLF); // 9*CPW words (bit-packed 3z-AND)

    const int tid = threadIdx.x;
    const int b   = blockIdx.y / ZC;
    const int zi  = blockIdx.y % ZC;
    const int z0  = 1 + zi * 10 + min(zi, 2);      // chunks 11,11,10,10,10,10
    const int z1  = z0 + ((zi < 2) ? 10 : 9);      // z1 <= 62
    const int y0  = 1 + blockIdx.x * TY;

    const float* mb = M + (long long)b * CH;
    const float* uP = P + ((long long)b * Cn + 1) * CH;
    const float* uT = T + ((long long)b * Cn + 1) * CH;
    const float* vP = uP + CH;  const float* vT = uT + CH;
    const float* wP = vP + CH;  const float* wT = vT + CH;

    // staging slot A (all threads) and slot B (even threads), 576 = 384 + 192
    const int  rA  = tid >> 6, gA = tid & 63, x4A = gA << 2;
    const int  roA = rA * Wn + x4A;
    const long long rbA = (long long)min(y0 - 1 + rA, Hn - 1) * Wn + x4A;
    const bool hasB = (tid & 1) == 0;
    const int  sB  = 384 + (tid >> 1);
    const int  rB  = sB >> 6, gB = sB & 63, x4B = gB << 2;
    const int  roB = rB * Wn + x4B;
    const long long rbB = (long long)min(y0 - 1 + rB, Hn - 1) * Wn + x4B;
    const int  lane = tid & 31;

    // zero CP pad words (j=8,9) once
    if (tid < 18) sCP[(tid / 2) * CPW + 8 + (tid & 1)] = 0u;

    // rolling packed masks: m(z-1), m(z) per slot
    unsigned mA0, mA1, mB0 = 0u, mB1 = 0u;
    #pragma unroll
    for (int k = 0; k < 2; ++k) {
        const int zz = z0 - 1 + k, su = zz % 3;
        const long long pb = (long long)zz * HW + rbA;
        *(float4*)(sU + su * PLF + roA) = f4sub(*(const float4*)(uP + pb), *(const float4*)(uT + pb));
        *(float4*)(sV + su * PLF + roA) = f4sub(*(const float4*)(vP + pb), *(const float4*)(vT + pb));
        const unsigned m = packm(*(const float4*)(mb + pb));
        if (k == 0) mA0 = m; else mA1 = m;
        if (hasB) {
            const long long pbx = (long long)zz * HW + rbB;
            *(float4*)(sU + su * PLF + roB) = f4sub(*(const float4*)(uP + pbx), *(const float4*)(uT + pbx));
            *(float4*)(sV + su * PLF + roB) = f4sub(*(const float4*)(vP + pbx), *(const float4*)(vT + pbx));
            const unsigned mx = packm(*(const float4*)(mb + pbx));
            if (k == 0) mB0 = mx; else mB1 = mx;
        }
    }
    // no sync needed: first in-loop sync orders these before any consume

    float fs  = 0.f;
    int   cnt = 0;

    for (int z = z0; z <= z1; ++z) {
        const int szm = (z - 1) % 3, sz = z % 3, szp = (z + 1) % 3;

        // ---- phase A: stage u,v(z+1), w(z), m(z+1); build CP(z) bits ----
        {
            const long long pb  = (long long)(z + 1) * HW + rbA;
            const long long pbw = (long long)z * HW + rbA;
            *(float4*)(sU + szp * PLF + roA) = f4sub(*(const float4*)(uP + pb), *(const float4*)(uT + pb));
            *(float4*)(sV + szp * PLF + roA) = f4sub(*(const float4*)(vP + pb), *(const float4*)(vT + pb));
            *(float4*)(sW + roA)             = f4sub(*(const float4*)(wP + pbw), *(const float4*)(wT + pbw));
            const unsigned m  = packm(*(const float4*)(mb + pb));
            const unsigned cp = mA0 & mA1 & m;
            mA0 = mA1; mA1 = m;
            // pack 8 nibbles -> word via warp OR-reduce (8-lane groups)
            unsigned v = nib4(cp) << ((gA & 7) * 4);
            v |= __shfl_xor_sync(0xffffffffu, v, 1);
            v |= __shfl_xor_sync(0xffffffffu, v, 2);
            v |= __shfl_xor_sync(0xffffffffu, v, 4);
            if ((gA & 7) == 0) sCP[rA * CPW + (gA >> 3)] = v;

            // slot B: even lanes only; 16-lane groups (8 data nibbles + 8 zeros)
            unsigned vb = 0u;
            if (hasB) {
                const long long pbx  = (long long)(z + 1) * HW + rbB;
                const long long pbwx = (long long)z * HW + rbB;
                *(float4*)(sU + szp * PLF + roB) = f4sub(*(const float4*)(uP + pbx), *(const float4*)(uT + pbx));
                *(float4*)(sV + szp * PLF + roB) = f4sub(*(const float4*)(vP + pbx), *(const float4*)(vT + pbx));
                *(float4*)(sW + roB)             = f4sub(*(const float4*)(wP + pbwx), *(const float4*)(wT + pbwx));
                const unsigned mx  = packm(*(const float4*)(mb + pbx));
                const unsigned cpx = mB0 & mB1 & mx;
                mB0 = mB1; mB1 = mx;
                vb = nib4(cpx) << ((gB & 7) * 4);
            }
            vb |= __shfl_xor_sync(0xffffffffu, vb, 2);
            vb |= __shfl_xor_sync(0xffffffffu, vb, 4);
            vb |= __shfl_xor_sync(0xffffffffu, vb, 8);
            if ((lane & 15) == 0) sCP[rB * CPW + (gB >> 3)] = vb;
        }
        __syncthreads();

        // ---- phase B: consume plane z (1792 outputs over 5 passes) ----
        #pragma unroll
        for (int p = 0; p < 5; ++p) {
            const int o = p * 384 + tid;
            if (o < TY * Wn) {
                const int r = (o >> 8) + 1;          // 1..7
                const int x = o & 255;
                const int y = y0 - 1 + r;
                if (x >= 1 && x <= Wn - 2 && y <= Hn - 2) {
                    const int      sh = (x - 1) & 31, j = (x - 1) >> 5;
                    unsigned ok3 = 0xFFFFFFFFu;
                    #pragma unroll
                    for (int dr = -1; dr <= 1; ++dr) {
                        const int wbase = (r + dr) * CPW + j;
                        ok3 &= __funnelshift_r(sCP[wbase], sCP[wbase + 1], sh);
                    }
                    const int ok = ((ok3 & 7u) == 7u);

                    const float dyU = sU[sz * PLF + (r + 1) * Wn + x] - sU[sz * PLF + (r - 1) * Wn + x];
                    const float dzU = sU[szp * PLF + r * Wn + x]      - sU[szm * PLF + r * Wn + x];
                    const float dyW = sW[(r + 1) * Wn + x]            - sW[(r - 1) * Wn + x];
                    const float dxW = sW[r * Wn + x + 1]              - sW[r * Wn + x - 1];
                    const float dxV = sV[sz * PLF + r * Wn + x + 1]   - sV[sz * PLF + r * Wn + x - 1];
                    const float dzV = sV[szp * PLF + r * Wn + x]      - sV[szm * PLF + r * Wn + x];

                    const float ox = dyW - dzV;
                    const float oy = dzU - dxW;
                    const float oz = dxV - dyU;
                    fs  += (float)ok * sqrtf(ox * ox + oy * oy + oz * oz);
                    cnt += ok;
                }
            }
        }
        __syncthreads();   // protects w/CP depth-1 and u/v slot reuse next iter
    }

    // ---- block reduction (12 warps) -> partial; last block finalizes ----
    #pragma unroll
    for (int off = 16; off; off >>= 1) {
        fs  += __shfl_down_sync(0xffffffffu, fs,  off);
        cnt += __shfl_down_sync(0xffffffffu, cnt, off);
    }
    __shared__ float ws[12];
    __shared__ int   wc2[12];
    __shared__ bool  sLast;
    const int wid = tid >> 5;
    if (lane == 0) { ws[wid] = fs; wc2[wid] = cnt; }
    __syncthreads();
    if (wid == 0) {
        fs  = (lane < 12) ? ws[lane]  : 0.f;
        cnt = (lane < 12) ? wc2[lane] : 0;
        #pragma unroll
        for (int off = 8; off; off >>= 1) {
            fs  += __shfl_down_sync(0xffffffffu, fs,  off);
            cnt += __shfl_down_sync(0xffffffffu, cnt, off);
        }
        if (lane == 0) {
            const int slot = blockIdx.y * NYT + blockIdx.x;
            g_psum[slot] = fs;
            g_pcnt[slot] = (unsigned)cnt;
            __threadfence();
            const unsigned t = atomicAdd(&g_ticket, 1u);
            sLast = (t == NBLK - 1);
        }
    }
    __syncthreads();

    if (sLast) {
        // Deterministic final reduce: fixed order over 444 slots, double accum.
        double             s = 0.0;
        unsigned long long c = 0ull;
        for (int i = tid; i < NBLK; i += 384) {
            s += (double)__ldcg(&g_psum[i]);
            c += (unsigned long long)__ldcg(&g_pcnt[i]);
        }
        #pragma unroll
        for (int off = 16; off; off >>= 1) {
            s += __shfl_down_sync(0xffffffffu, s, off);
            c += __shfl_down_sync(0xffffffffu, c, off);
        }
        __shared__ double             ds[12];
        __shared__ unsigned long long dc[12];
        if (lane == 0) { ds[wid] = s; dc[wid] = c; }
        __syncthreads();
        if (wid == 0) {
            s = (lane < 12) ? ds[lane] : 0.0;
            c = (lane < 12) ? dc[lane] : 0ull;
            #pragma unroll
            for (int off = 8; off; off >>= 1) {
                s += __shfl_down_sync(0xffffffffu, s, off);
                c += __shfl_down_sync(0xffffffffu, c, off);
            }
            if (lane == 0) {
                out[0] = (float)(s / (double)c);
                g_ticket = 0;                      // reset for next graph replay
            }
        }
    }
}

extern "C" void kernel_launch(void* const* d_in, const int* in_sizes, int n_in,
                              void* d_out, int out_size) {
    const float* P = (const float*)d_in[0];
    const float* T = (const float*)d_in[1];
    const float* M = (const float*)d_in[2];
    float*       O = (float*)d_out;

    cudaFuncSetAttribute(k_main, cudaFuncAttributeMaxDynamicSharedMemorySize, SMEM_BYTES);
    k_main<<<dim3(NYT, 2 * ZC), 384, SMEM_BYTES>>>(P, T, M, O);
}